// round 17
// baseline (speedup 1.0000x reference)
#include <cuda_runtime.h>
#include <cstddef>

// Problem constants
#define BB 16      // batch
#define TT 2048    // text len
#define EE 768     // embed dim
#define E4 (EE/4)  // 192 float4 per row
#define SS 32      // num sentences
#define LL 64      // max sent len
#define NT 128     // t-chunks (blocks) per batch
#define TCH (TT / NT)   // 16 timesteps per chunk

// Scratch (no device allocation allowed -> __device__ globals)
__device__ float4 g_partial4[BB * NT * E4];  // 6.3MB partial sums (b, chunk, e4)
__device__ int    g_cnt[BB];                 // zero-init; reset by elected block

// ---------------------------------------------------------------------------
// Single fused kernel.
// Phase 1 (all 2048 blocks): mean-pool partials + speculative identity copy
//   (out[B,S,L,E] flattened == in[B,T,E] when every start==s*64 && len==64,
//    which holds unless an offset >= 1.0: sigma(offset)~0.012 => never).
// Phase 2 (last block per batch, elected via threadfence+atomic): reduce
//   partials, GEMV offsets = pooled@W + b, exact reference index math, and
//   patch any sentence whose (start,len) != identity. Correct for arbitrary
//   data; near-zero work for this distribution.
// Election is order-insensitive: the elected block's computation is identical
// whichever block arrives last -> deterministic output.
// ---------------------------------------------------------------------------
__global__ __launch_bounds__(192) void k_fused(const float4* __restrict__ in,
                                               float4* __restrict__ out,
                                               const float* __restrict__ W,
                                               const float* __restrict__ bias) {
    const int blk = blockIdx.x;
    const int b = blk >> 7;          // / NT
    const int c = blk & (NT - 1);    // % NT
    const int tid = threadIdx.x;     // 0..191 == e4 column

    // ---------------- Phase 1: pool + speculative copy ----------------
    {
        const size_t row0 = (size_t)b * TT + (size_t)c * TCH;
        const float4* src = in + row0 * E4 + tid;
        float4* dst = out + row0 * E4 + tid;   // identity layout

        float4 a0 = make_float4(0.f, 0.f, 0.f, 0.f);
        float4 a1 = make_float4(0.f, 0.f, 0.f, 0.f);
        float4 a2 = make_float4(0.f, 0.f, 0.f, 0.f);
        float4 a3 = make_float4(0.f, 0.f, 0.f, 0.f);
#pragma unroll
        for (int t = 0; t < TCH; t += 4) {
            float4 v0 = src[(size_t)(t + 0) * E4];
            float4 v1 = src[(size_t)(t + 1) * E4];
            float4 v2 = src[(size_t)(t + 2) * E4];
            float4 v3 = src[(size_t)(t + 3) * E4];
            a0.x += v0.x; a0.y += v0.y; a0.z += v0.z; a0.w += v0.w;
            a1.x += v1.x; a1.y += v1.y; a1.z += v1.z; a1.w += v1.w;
            a2.x += v2.x; a2.y += v2.y; a2.z += v2.z; a2.w += v2.w;
            a3.x += v3.x; a3.y += v3.y; a3.z += v3.z; a3.w += v3.w;
            __stcs(&dst[(size_t)(t + 0) * E4], v0);
            __stcs(&dst[(size_t)(t + 1) * E4], v1);
            __stcs(&dst[(size_t)(t + 2) * E4], v2);
            __stcs(&dst[(size_t)(t + 3) * E4], v3);
        }
        float4 s;
        s.x = (a0.x + a1.x) + (a2.x + a3.x);
        s.y = (a0.y + a1.y) + (a2.y + a3.y);
        s.z = (a0.z + a1.z) + (a2.z + a3.z);
        s.w = (a0.w + a1.w) + (a2.w + a3.w);
        g_partial4[(size_t)(b * NT + c) * E4 + tid] = s;
    }

    // ---------------- Election: last block of batch b ----------------
    __shared__ int is_last;
    __threadfence();                 // release this block's partial+out stores
    __syncthreads();
    if (tid == 0) {
        int old = atomicAdd(&g_cnt[b], 1);
        is_last = (old == NT - 1);
    }
    __syncthreads();
    if (!is_last) return;

    // ---------------- Phase 2 (elected block only) ----------------
    __shared__ float pooled[EE];
    __shared__ float red[3][2 * SS];
    __shared__ int   s_start[SS];
    __shared__ int   s_len[SS];
    __shared__ int   s_dirty[SS];

    // Reduce 128 partial rows for this batch; 8-way batched loads (few L2
    // round-trips instead of a 64-deep dependent chain).
    {
        const float4* p = g_partial4 + (size_t)b * NT * E4 + tid;
        float4 acc0 = make_float4(0.f, 0.f, 0.f, 0.f);
        float4 acc1 = make_float4(0.f, 0.f, 0.f, 0.f);
#pragma unroll
        for (int c2 = 0; c2 < NT; c2 += 8) {
            float4 r0 = p[(size_t)(c2 + 0) * E4];
            float4 r1 = p[(size_t)(c2 + 1) * E4];
            float4 r2 = p[(size_t)(c2 + 2) * E4];
            float4 r3 = p[(size_t)(c2 + 3) * E4];
            float4 r4 = p[(size_t)(c2 + 4) * E4];
            float4 r5 = p[(size_t)(c2 + 5) * E4];
            float4 r6 = p[(size_t)(c2 + 6) * E4];
            float4 r7 = p[(size_t)(c2 + 7) * E4];
            acc0.x += ((r0.x + r1.x) + (r2.x + r3.x));
            acc0.y += ((r0.y + r1.y) + (r2.y + r3.y));
            acc0.z += ((r0.z + r1.z) + (r2.z + r3.z));
            acc0.w += ((r0.w + r1.w) + (r2.w + r3.w));
            acc1.x += ((r4.x + r5.x) + (r6.x + r7.x));
            acc1.y += ((r4.y + r5.y) + (r6.y + r7.y));
            acc1.z += ((r4.z + r5.z) + (r6.z + r7.z));
            acc1.w += ((r4.w + r5.w) + (r6.w + r7.w));
        }
        const float inv = 1.0f / (float)TT;
        pooled[4 * tid + 0] = (acc0.x + acc1.x) * inv;
        pooled[4 * tid + 1] = (acc0.y + acc1.y) * inv;
        pooled[4 * tid + 2] = (acc0.z + acc1.z) * inv;
        pooled[4 * tid + 3] = (acc0.w + acc1.w) * inv;
    }
    __syncthreads();

    // GEMV: 192 threads = 64 cols x 3 e-segments of 256.
    {
        const int col = tid & (2 * SS - 1);   // 0..63
        const int seg = tid >> 6;             // 0..2
        float acc = 0.f;
        const int e0 = seg * 256;
#pragma unroll 8
        for (int e = e0; e < e0 + 256; e++)
            acc = fmaf(pooled[e], W[e * (2 * SS) + col], acc);
        red[seg][col] = acc;
    }
    __syncthreads();

    // Exact reference index math (truncation == floor for nonneg):
    //   start_off = (int)clip(off_s, 0, 63); end_off = (int)clip(off_{s+32},0,63)
    //   start = clip(s*64+start_off, 0, T-L); end = clip(s*64+64+end_off, start, T)
    if (tid < SS) {
        const int s = tid;
        const float off1 = red[0][s] + red[1][s] + red[2][s] + bias[s];
        const float off2 = red[0][s + SS] + red[1][s + SS] + red[2][s + SS] + bias[s + SS];

        const int so = (int)fminf(fmaxf(off1, 0.f), (float)(LL - 1));
        const int eo = (int)fminf(fmaxf(off2, 0.f), (float)(LL - 1));

        const int basei = s * LL;
        int start = basei + so;
        if (start > TT - LL) start = TT - LL;
        if (start < 0) start = 0;
        int end = basei + LL + eo;
        if (end < start) end = start;
        if (end > TT) end = TT;

        const int len = end - start;
        s_start[s] = start;
        s_len[s]   = len;
        s_dirty[s] = (start != basei) | (len != LL);
    }
    __syncthreads();

    // Patch dirty sentences (rewrite completely; rare-to-never).
    for (int s = 0; s < SS; s++) {
        if (!s_dirty[s]) continue;
        const int start = s_start[s];
        const int len   = s_len[s];
        const float4* src = in + ((size_t)b * TT + (size_t)start) * E4 + tid;
        float4* dst = out + ((size_t)(b * SS + s) * LL) * E4 + tid;
        for (int j = 0; j < LL; j++) {
            float4 v = (j < len) ? src[(size_t)j * E4]
                                 : make_float4(0.f, 0.f, 0.f, 0.f);
            dst[(size_t)j * E4] = v;
        }
    }

    // Reset counter for the next graph replay.
    if (tid == 0) g_cnt[b] = 0;
}

// ---------------------------------------------------------------------------
// Entry point. Inputs (metadata order): inputs f32 [B,T,E], W f32 [E,2S],
// b f32 [2S]. Output f32 [B,S,L,E]. One launch, no inter-kernel gaps.
// ---------------------------------------------------------------------------
extern "C" void kernel_launch(void* const* d_in, const int* in_sizes, int n_in,
                              void* d_out, int out_size) {
    const float4* in  = (const float4*)d_in[0];
    const float* W    = (const float*)d_in[1];
    const float* bias = (const float*)d_in[2];
    float4* out       = (float4*)d_out;

    k_fused<<<BB * NT, 192>>>(in, out, W, bias);
}